// round 3
// baseline (speedup 1.0000x reference)
#include <cuda_runtime.h>

#define EPSV 1e-5f
#define RSQRT8 0.35355339059327373f

// scratch (allocation-free rule: device globals)
__device__ float g_q[4*512*64];
__device__ float g_k[4*512*64];
__device__ float g_v[4*512*64];

typedef unsigned long long ull;

__device__ __forceinline__ ull splat2(float x){
    ull r; unsigned u = __float_as_uint(x);
    asm("mov.b64 %0, {%1,%1};" : "=l"(r) : "r"(u));
    return r;
}
__device__ __forceinline__ void fma2a(ull& d, ull a, ull b){
    asm("fma.rn.f32x2 %0, %1, %2, %0;" : "+l"(d) : "l"(a), "l"(b));
}
__device__ __forceinline__ ull mul2(ull a, ull b){
    ull d; asm("mul.rn.f32x2 %0, %1, %2;" : "=l"(d) : "l"(a), "l"(b));
    return d;
}
__device__ __forceinline__ void add2a(ull& d, ull a){
    asm("add.rn.f32x2 %0, %0, %1;" : "+l"(d) : "l"(a));
}
__device__ __forceinline__ float2 unpack2(ull v){
    unsigned lo, hi;
    asm("mov.b64 {%0,%1}, %2;" : "=r"(lo), "=r"(hi) : "l"(v));
    return make_float2(__uint_as_float(lo), __uint_as_float(hi));
}
__device__ __forceinline__ void cpa16(void* sd, const void* g){
    unsigned s = (unsigned)__cvta_generic_to_shared(sd);
    asm volatile("cp.async.cg.shared.global [%0], [%1], 16;" :: "r"(s), "l"(g));
}

// ===================== Kernel 1: LN1 + QKV projection =====================
__global__ void qkv_kernel(const float* __restrict__ h, const float* __restrict__ Wh,
                           const float* __restrict__ g1, const float* __restrict__ b1)
{
    __shared__ float hn[64];
    __shared__ float part[4];
    int row = blockIdx.x, t = threadIdx.x;
    float x = h[row*64 + t];
    float s = x, q = x*x;
    #pragma unroll
    for (int o = 16; o >= 1; o >>= 1){
        s += __shfl_xor_sync(0xffffffffu, s, o);
        q += __shfl_xor_sync(0xffffffffu, q, o);
    }
    if ((t & 31) == 0){ part[t>>5] = s; part[2 + (t>>5)] = q; }
    __syncthreads();
    float mean = (part[0] + part[1]) * (1.f/64.f);
    float var  = (part[2] + part[3]) * (1.f/64.f) - mean*mean;
    float hv = (x - mean) * rsqrtf(var + EPSV) * g1[t] + b1[t];
    hn[t] = hv;
    __syncthreads();
    float aq = 0.f, ak = 0.f, av = 0.f;
    #pragma unroll 8
    for (int i = 0; i < 64; i++){
        float z = hn[i];
        aq = fmaf(z, Wh[i*192 + t],       aq);
        ak = fmaf(z, Wh[i*192 + 64 + t],  ak);
        av = fmaf(z, Wh[i*192 + 128 + t], av);
    }
    g_q[row*64 + t] = aq;
    g_k[row*64 + t] = ak;
    g_v[row*64 + t] = av;
}

// ===================== Kernel 2: fused edge-GEMM + attention + LN2 + MLP =====================
// Block: 256 threads = 8 warps. Warp w owns q-row (w>>1) and head-group (w&1)
// (4 heads each); lane = k within 32-wide tile.
// smem layout identical to R2 (2 blocks/SM, 114688 B dynamic):
//   e_s[2][128][68], k_s[2][32][68], v_s[2][32][68], we_s[1024],
//   y_s[256], z_s[256], hid_s[1024]
__global__ void __launch_bounds__(256, 2)
attn_kernel(const float* __restrict__ e, const float* __restrict__ We,
            const float* __restrict__ hin, const float* __restrict__ w1,
            const float* __restrict__ w2, const float* __restrict__ g2,
            const float* __restrict__ b2, float* __restrict__ out)
{
    extern __shared__ float smem[];
    float* e_s   = smem;
    float* k_s   = smem + 17408;
    float* v_s   = smem + 21760;
    float* we_s  = smem + 26112;
    float* y_s   = smem + 27136;
    float* z_s   = smem + 27392;
    float* hid_s = smem + 27648;

    const int t    = threadIdx.x;
    const int w    = t >> 5;
    const int lane = t & 31;
    const int qr   = w >> 1;          // q row within tile (0..3)
    const int hg   = w & 1;           // head group (heads 4*hg .. 4*hg+3)
    const int hb2  = hg << 1;         // ull column offset into W_e row
    const int qt   = blockIdx.x;
    const int b    = qt >> 7;           // 128 q-tiles per batch
    const int q0   = (qt & 127) << 2;   // 4 q rows per tile

    const float* eg = e + ((size_t)(b*512 + q0)) * 512 * 64;
    const float* kg = g_k + (size_t)(b*512) * 64;
    const float* vg = g_v + (size_t)(b*512) * 64;

    // preload this warp's 4 heads of the q row (32 floats = 16 packed pairs)
    ull qp[16];
    {
        const ull* qgp = (const ull*)(g_q + (size_t)(b*512 + q0 + qr) * 64);
        #pragma unroll
        for (int i = 0; i < 16; i++) qp[i] = qgp[hg*16 + i];
    }

    // ---- issue tile 0 (+ W_e) into buffer 0 ----
    {
        #pragma unroll
        for (int it = 0; it < 8; it++){
            int f = t + it*256; int row = f >> 4, c = f & 15;
            int qq = row >> 5, kk = row & 31;
            cpa16(e_s + row*68 + c*4, eg + (size_t)qq*32768 + (size_t)kk*64 + c*4);
        }
        #pragma unroll
        for (int it = 0; it < 2; it++){
            int f = t + it*256; int row = f >> 4, c = f & 15;
            cpa16(k_s + row*68 + c*4, kg + (size_t)row*64 + c*4);
            cpa16(v_s + row*68 + c*4, vg + (size_t)row*64 + c*4);
        }
        cpa16(we_s + t*4, We + t*4);
        asm volatile("cp.async.commit_group;");
    }

    float l[4];
    ull acc[16];
    #pragma unroll
    for (int hh = 0; hh < 4; hh++) l[hh] = 0.f;
    #pragma unroll
    for (int i = 0; i < 16; i++) acc[i] = 0ull;

    for (int tile = 0; tile < 16; tile++){
        const int buf = tile & 1;
        if (tile < 15){
            const int nb = (tile + 1) & 1;
            const int k0 = (tile + 1) * 32;
            float* ed = e_s + nb*8704;
            float* kd = k_s + nb*2176;
            float* vd = v_s + nb*2176;
            #pragma unroll
            for (int it = 0; it < 8; it++){
                int f = t + it*256; int row = f >> 4, c = f & 15;
                int qq = row >> 5, kk = row & 31;
                cpa16(ed + row*68 + c*4, eg + (size_t)qq*32768 + (size_t)(k0+kk)*64 + c*4);
            }
            #pragma unroll
            for (int it = 0; it < 2; it++){
                int f = t + it*256; int row = f >> 4, c = f & 15;
                cpa16(kd + row*68 + c*4, kg + (size_t)(k0+row)*64 + c*4);
                cpa16(vd + row*68 + c*4, vg + (size_t)(k0+row)*64 + c*4);
            }
            asm volatile("cp.async.commit_group;");
            asm volatile("cp.async.wait_group 1;");
        } else {
            asm volatile("cp.async.wait_group 0;");
        }
        __syncthreads();

        // ---- ew (this warp's 8 of 16 outputs): packed f32x2 FMA ----
        const float4* erow = (const float4*)(e_s + buf*8704 + (qr*32 + lane)*68);
        const ull* weP = (const ull*)we_s;
        ull ew0 = 0ull, ew1 = 0ull, ew2 = 0ull, ew3 = 0ull;
        #pragma unroll
        for (int i4 = 0; i4 < 16; i4++){
            float4 ev = erow[i4];
            float evv[4] = {ev.x, ev.y, ev.z, ev.w};
            #pragma unroll
            for (int c = 0; c < 4; c++){
                ull es = splat2(evv[c]);
                const ull* wr = weP + (i4*4 + c)*8;
                fma2a(ew0, es, wr[hb2]);
                fma2a(ew1, es, wr[hb2 + 1]);
                fma2a(ew2, es, wr[4 + hb2]);
                fma2a(ew3, es, wr[5 + hb2]);
            }
        }
        float e1[4], e2v[4];
        { float2 u = unpack2(ew0); e1[0] = u.x;  e1[1] = u.y; }
        { float2 u = unpack2(ew1); e1[2] = u.x;  e1[3] = u.y; }
        { float2 u = unpack2(ew2); e2v[0] = u.x; e2v[1] = u.y; }
        { float2 u = unpack2(ew3); e2v[2] = u.x; e2v[3] = u.y; }

        // ---- per-head: logit, exp (no max needed: |logit| << 80), gated PV ----
        const ulonglong2* kr = (const ulonglong2*)(k_s + buf*2176 + lane*68);
        const ulonglong2* vr = (const ulonglong2*)(v_s + buf*2176 + lane*68);
        #pragma unroll
        for (int hh = 0; hh < 4; hh++){
            const int H = hg*4 + hh;
            ulonglong2 ka = kr[2*H], kb = kr[2*H+1];
            ull s2 = mul2(qp[4*hh], ka.x);
            fma2a(s2, qp[4*hh+1], ka.y);
            fma2a(s2, qp[4*hh+2], kb.x);
            fma2a(s2, qp[4*hh+3], kb.y);
            float2 sp = unpack2(s2);
            float s = fmaf(sp.x + sp.y, RSQRT8, e1[hh]);
            float p = __expf(s);
            l[hh] += p;
            ull gg = splat2(p * e2v[hh]);
            ulonglong2 va = vr[2*H], vb = vr[2*H+1];
            fma2a(acc[4*hh+0], gg, va.x);
            fma2a(acc[4*hh+1], gg, va.y);
            fma2a(acc[4*hh+2], gg, vb.x);
            fma2a(acc[4*hh+3], gg, vb.y);
        }
        __syncthreads();
    }

    // ---- cross-lane butterfly sum of (l, acc) ----
    #pragma unroll
    for (int off = 16; off >= 1; off >>= 1){
        #pragma unroll
        for (int hh = 0; hh < 4; hh++){
            l[hh] += __shfl_xor_sync(0xffffffffu, l[hh], off);
            add2a(acc[4*hh+0], __shfl_xor_sync(0xffffffffu, acc[4*hh+0], off));
            add2a(acc[4*hh+1], __shfl_xor_sync(0xffffffffu, acc[4*hh+1], off));
            add2a(acc[4*hh+2], __shfl_xor_sync(0xffffffffu, acc[4*hh+2], off));
            add2a(acc[4*hh+3], __shfl_xor_sync(0xffffffffu, acc[4*hh+3], off));
        }
    }

    if (lane == 0){
        #pragma unroll
        for (int hh = 0; hh < 4; hh++){
            const int H = hg*4 + hh;
            float inv = __fdividef(1.f, l[hh]);
            #pragma unroll
            for (int d2 = 0; d2 < 4; d2++){
                float2 u = unpack2(acc[4*hh + d2]);
                y_s[qr*64 + H*8 + d2*2]     = u.x * inv;
                y_s[qr*64 + H*8 + d2*2 + 1] = u.y * inv;
            }
        }
    }
    __syncthreads();

    // ---- LN2 over (y + h_in), per-row (warps 0..3 = rows 0..3) ----
    if (w < 4){
        const float* hrow = hin + (size_t)(b*512 + q0 + w) * 64;
        float x0 = y_s[w*64 + lane]      + hrow[lane];
        float x1 = y_s[w*64 + lane + 32] + hrow[lane + 32];
        float s = x0 + x1, sq = x0*x0 + x1*x1;
        #pragma unroll
        for (int o = 16; o >= 1; o >>= 1){
            s  += __shfl_xor_sync(0xffffffffu, s, o);
            sq += __shfl_xor_sync(0xffffffffu, sq, o);
        }
        float mean = s * (1.f/64.f);
        float var  = sq * (1.f/64.f) - mean*mean;
        float rs = rsqrtf(var + EPSV);
        z_s[w*64 + lane]      = (x0 - mean) * rs * g2[lane]      + b2[lane];
        z_s[w*64 + lane + 32] = (x1 - mean) * rs * g2[lane + 32] + b2[lane + 32];
    }
    __syncthreads();

    // ---- hidden = relu(z @ w1)  [4 x 256], one column per thread ----
    {
        int jj = t;
        float a0 = 0.f, a1 = 0.f, a2 = 0.f, a3 = 0.f;
        #pragma unroll 8
        for (int i = 0; i < 64; i++){
            float wv = w1[i*256 + jj];
            a0 = fmaf(z_s[i],       wv, a0);
            a1 = fmaf(z_s[64 + i],  wv, a1);
            a2 = fmaf(z_s[128 + i], wv, a2);
            a3 = fmaf(z_s[192 + i], wv, a3);
        }
        hid_s[jj]       = fmaxf(a0, 0.f);
        hid_s[256 + jj] = fmaxf(a1, 0.f);
        hid_s[512 + jj] = fmaxf(a2, 0.f);
        hid_s[768 + jj] = fmaxf(a3, 0.f);
    }
    __syncthreads();

    // ---- out = hidden @ w2 + y : one output element per thread ----
    {
        int d = t & 63, r = t >> 6;
        float a = 0.f;
        #pragma unroll 8
        for (int j = 0; j < 256; j++)
            a = fmaf(hid_s[r*256 + j], w2[j*64 + d], a);
        out[((size_t)(b*512 + q0 + r)) * 64 + d] = a + y_s[r*64 + d];
    }
}

extern "C" void kernel_launch(void* const* d_in, const int* in_sizes, int n_in,
                              void* d_out, int out_size)
{
    const float* h  = (const float*)d_in[0];
    const float* e  = (const float*)d_in[1];
    const float* Wh = (const float*)d_in[2];
    const float* We = (const float*)d_in[3];
    const float* w1 = (const float*)d_in[4];
    const float* w2 = (const float*)d_in[5];
    const float* g1 = (const float*)d_in[6];
    const float* b1 = (const float*)d_in[7];
    const float* g2 = (const float*)d_in[8];
    const float* b2 = (const float*)d_in[9];
    float* out = (float*)d_out;

    cudaFuncSetAttribute(attn_kernel, cudaFuncAttributeMaxDynamicSharedMemorySize, 114688);

    qkv_kernel<<<2048, 64>>>(h, Wh, g1, b1);
    attn_kernel<<<512, 256, 114688>>>(e, We, h, w1, w2, g2, b2, out);
}

// round 4
// speedup vs baseline: 1.1759x; 1.1759x over previous
#include <cuda_runtime.h>

#define EPSV 1e-5f
#define RSQRT8 0.35355339059327373f

// scratch (allocation-free rule: device globals)
__device__ float g_q[4*512*64];
__device__ float g_k[4*512*64];
__device__ float g_v[4*512*64];

typedef unsigned long long ull;

__device__ __forceinline__ ull splat2(float x){
    ull r; unsigned u = __float_as_uint(x);
    asm("mov.b64 %0, {%1,%1};" : "=l"(r) : "r"(u));
    return r;
}
__device__ __forceinline__ void fma2a(ull& d, ull a, ull b){
    asm("fma.rn.f32x2 %0, %1, %2, %0;" : "+l"(d) : "l"(a), "l"(b));
}
__device__ __forceinline__ ull mul2(ull a, ull b){
    ull d; asm("mul.rn.f32x2 %0, %1, %2;" : "=l"(d) : "l"(a), "l"(b));
    return d;
}
__device__ __forceinline__ void add2a(ull& d, ull a){
    asm("add.rn.f32x2 %0, %0, %1;" : "+l"(d) : "l"(a));
}
__device__ __forceinline__ float2 unpack2(ull v){
    unsigned lo, hi;
    asm("mov.b64 {%0,%1}, %2;" : "=r"(lo), "=r"(hi) : "l"(v));
    return make_float2(__uint_as_float(lo), __uint_as_float(hi));
}
__device__ __forceinline__ void cpa16(void* sd, const void* g){
    unsigned s = (unsigned)__cvta_generic_to_shared(sd);
    asm volatile("cp.async.cg.shared.global [%0], [%1], 16;" :: "r"(s), "l"(g));
}

// ===================== Kernel 1: LN1 + QKV projection =====================
__global__ void qkv_kernel(const float* __restrict__ h, const float* __restrict__ Wh,
                           const float* __restrict__ g1, const float* __restrict__ b1)
{
    __shared__ float hn[64];
    __shared__ float part[4];
    int row = blockIdx.x, t = threadIdx.x;
    float x = h[row*64 + t];
    float s = x, q = x*x;
    #pragma unroll
    for (int o = 16; o >= 1; o >>= 1){
        s += __shfl_xor_sync(0xffffffffu, s, o);
        q += __shfl_xor_sync(0xffffffffu, q, o);
    }
    if ((t & 31) == 0){ part[t>>5] = s; part[2 + (t>>5)] = q; }
    __syncthreads();
    float mean = (part[0] + part[1]) * (1.f/64.f);
    float var  = (part[2] + part[3]) * (1.f/64.f) - mean*mean;
    float hv = (x - mean) * rsqrtf(var + EPSV) * g1[t] + b1[t];
    hn[t] = hv;
    __syncthreads();
    float aq = 0.f, ak = 0.f, av = 0.f;
    #pragma unroll 8
    for (int i = 0; i < 64; i++){
        float z = hn[i];
        aq = fmaf(z, Wh[i*192 + t],       aq);
        ak = fmaf(z, Wh[i*192 + 64 + t],  ak);
        av = fmaf(z, Wh[i*192 + 128 + t], av);
    }
    g_q[row*64 + t] = aq;
    g_k[row*64 + t] = ak;
    g_v[row*64 + t] = av;
}

// ===================== Kernel 2: fused edge-GEMM + attention + LN2 + MLP =====================
// Block: 256 threads = 8 warps, owns 8 q-rows. Warp w: q-pair qp=w>>1 (rows 2qp,2qp+1),
// head-group hg=w&1 (4 heads). lane = k within 32-wide k-tile.
// Weights amortized over 2 q-rows, loaded as LDS.128 pairs.
// smem (floats): e_s[2][256][68]=34816, k_s[2][32][68]=4352, v_s=4352,
//   we_s=1024, q_s=512, y_s=512, z_s=512, hid_s=2048  -> 48128 fl = 192512 B (1 blk/SM)
__global__ void __launch_bounds__(256, 1)
attn_kernel(const float* __restrict__ e, const float* __restrict__ We,
            const float* __restrict__ hin, const float* __restrict__ w1,
            const float* __restrict__ w2, const float* __restrict__ g2,
            const float* __restrict__ b2, float* __restrict__ out)
{
    extern __shared__ float smem[];
    float* e_s   = smem;
    float* k_s   = smem + 34816;
    float* v_s   = smem + 39168;
    float* we_s  = smem + 43520;
    float* q_s   = smem + 44544;
    float* y_s   = smem + 45056;
    float* z_s   = smem + 45568;
    float* hid_s = smem + 46080;

    const int t    = threadIdx.x;
    const int w    = t >> 5;
    const int lane = t & 31;
    const int qp   = w >> 1;          // q-pair: rows 2qp, 2qp+1 (of 8)
    const int hg   = w & 1;           // head group (heads 4*hg..4*hg+3)
    const int r0   = qp << 1;
    const int bx   = blockIdx.x;
    const int b    = bx >> 6;           // 64 blocks per batch
    const int q0   = (bx & 63) << 3;    // 8 q rows per block

    const float* eg = e + ((size_t)(b*512 + q0)) * 512 * 64;
    const float* kg = g_k + (size_t)(b*512) * 64;
    const float* vg = g_v + (size_t)(b*512) * 64;
    const float* qg = g_q + (size_t)(b*512 + q0) * 64;

    // ---- issue tile 0 (+ W_e + q rows) into buffer 0 ----
    {
        #pragma unroll
        for (int it = 0; it < 16; it++){
            int f = t + it*256; int row = f >> 4, c = f & 15;
            int qq = row >> 5, kk = row & 31;
            cpa16(e_s + row*68 + c*4, eg + (size_t)qq*32768 + (size_t)kk*64 + c*4);
        }
        #pragma unroll
        for (int it = 0; it < 2; it++){
            int f = t + it*256; int row = f >> 4, c = f & 15;
            cpa16(k_s + row*68 + c*4, kg + (size_t)row*64 + c*4);
            cpa16(v_s + row*68 + c*4, vg + (size_t)row*64 + c*4);
        }
        cpa16(we_s + t*4, We + t*4);
        if (t < 128) cpa16(q_s + t*4, qg + t*4);
        asm volatile("cp.async.commit_group;");
    }

    float l[8];
    ull acc[32];                      // [row(2)][head(4)][d2(4)]
    #pragma unroll
    for (int i = 0; i < 8; i++) l[i] = 0.f;
    #pragma unroll
    for (int i = 0; i < 32; i++) acc[i] = 0ull;

    for (int tile = 0; tile < 16; tile++){
        const int buf = tile & 1;
        if (tile < 15){
            const int nb = (tile + 1) & 1;
            const int k0 = (tile + 1) * 32;
            float* ed = e_s + nb*17408;
            float* kd = k_s + nb*2176;
            float* vd = v_s + nb*2176;
            #pragma unroll
            for (int it = 0; it < 16; it++){
                int f = t + it*256; int row = f >> 4, c = f & 15;
                int qq = row >> 5, kk = row & 31;
                cpa16(ed + row*68 + c*4, eg + (size_t)qq*32768 + (size_t)(k0+kk)*64 + c*4);
            }
            #pragma unroll
            for (int it = 0; it < 2; it++){
                int f = t + it*256; int row = f >> 4, c = f & 15;
                cpa16(kd + row*68 + c*4, kg + (size_t)(k0+row)*64 + c*4);
                cpa16(vd + row*68 + c*4, vg + (size_t)(k0+row)*64 + c*4);
            }
            asm volatile("cp.async.commit_group;");
            asm volatile("cp.async.wait_group 1;");
        } else {
            asm volatile("cp.async.wait_group 0;");
        }
        __syncthreads();

        // ---- ew for 2 q-rows (8 outputs each): weight LDS.128, amortized ----
        const float4* er0 = (const float4*)(e_s + buf*17408 + (r0*32 + lane)*68);
        const float4* er1 = er0 + 544;   // next q row (+32 rows of 68 floats)
        const ulonglong2* weV = (const ulonglong2*)we_s;
        ull ew00=0, ew01=0, ew02=0, ew03=0;
        ull ew10=0, ew11=0, ew12=0, ew13=0;
        #pragma unroll
        for (int i4 = 0; i4 < 16; i4++){
            float4 a0 = er0[i4];
            float4 a1 = er1[i4];
            float av0[4] = {a0.x, a0.y, a0.z, a0.w};
            float av1[4] = {a1.x, a1.y, a1.z, a1.w};
            #pragma unroll
            for (int c = 0; c < 4; c++){
                const int i = i4*4 + c;
                ulonglong2 w1v = weV[i*4 + hg];      // e1 pair for this head group
                ulonglong2 w2v = weV[i*4 + 2 + hg];  // e2 pair
                ull s0 = splat2(av0[c]);
                ull s1 = splat2(av1[c]);
                fma2a(ew00, s0, w1v.x); fma2a(ew01, s0, w1v.y);
                fma2a(ew02, s0, w2v.x); fma2a(ew03, s0, w2v.y);
                fma2a(ew10, s1, w1v.x); fma2a(ew11, s1, w1v.y);
                fma2a(ew12, s1, w2v.x); fma2a(ew13, s1, w2v.y);
            }
        }
        float e1a[8], e2a[8];  // [row*4 + head]
        { float2 u = unpack2(ew00); e1a[0] = u.x; e1a[1] = u.y; }
        { float2 u = unpack2(ew01); e1a[2] = u.x; e1a[3] = u.y; }
        { float2 u = unpack2(ew02); e2a[0] = u.x; e2a[1] = u.y; }
        { float2 u = unpack2(ew03); e2a[2] = u.x; e2a[3] = u.y; }
        { float2 u = unpack2(ew10); e1a[4] = u.x; e1a[5] = u.y; }
        { float2 u = unpack2(ew11); e1a[6] = u.x; e1a[7] = u.y; }
        { float2 u = unpack2(ew12); e2a[4] = u.x; e2a[5] = u.y; }
        { float2 u = unpack2(ew13); e2a[6] = u.x; e2a[7] = u.y; }

        // ---- per-head attention for both rows (k/v loads shared) ----
        const ulonglong2* kr  = (const ulonglong2*)(k_s + buf*2176 + lane*68);
        const ulonglong2* vr  = (const ulonglong2*)(v_s + buf*2176 + lane*68);
        const ulonglong2* q0v = (const ulonglong2*)(q_s + (r0)*64);
        const ulonglong2* q1v = (const ulonglong2*)(q_s + (r0+1)*64);
        #pragma unroll
        for (int hh = 0; hh < 4; hh++){
            const int H = hg*4 + hh;
            ulonglong2 ka = kr[2*H], kb = kr[2*H+1];
            ulonglong2 va = vr[2*H], vb = vr[2*H+1];
            ulonglong2 qa0 = q0v[2*H], qb0 = q0v[2*H+1];
            ulonglong2 qa1 = q1v[2*H], qb1 = q1v[2*H+1];
            // row 0
            {
                ull s2 = mul2(qa0.x, ka.x);
                fma2a(s2, qa0.y, ka.y);
                fma2a(s2, qb0.x, kb.x);
                fma2a(s2, qb0.y, kb.y);
                float2 sp = unpack2(s2);
                float s = fmaf(sp.x + sp.y, RSQRT8, e1a[hh]);
                float p = __expf(s);
                l[hh] += p;
                ull gg = splat2(p * e2a[hh]);
                fma2a(acc[4*hh+0], gg, va.x);
                fma2a(acc[4*hh+1], gg, va.y);
                fma2a(acc[4*hh+2], gg, vb.x);
                fma2a(acc[4*hh+3], gg, vb.y);
            }
            // row 1
            {
                ull s2 = mul2(qa1.x, ka.x);
                fma2a(s2, qa1.y, ka.y);
                fma2a(s2, qb1.x, kb.x);
                fma2a(s2, qb1.y, kb.y);
                float2 sp = unpack2(s2);
                float s = fmaf(sp.x + sp.y, RSQRT8, e1a[4+hh]);
                float p = __expf(s);
                l[4+hh] += p;
                ull gg = splat2(p * e2a[4+hh]);
                fma2a(acc[16+4*hh+0], gg, va.x);
                fma2a(acc[16+4*hh+1], gg, va.y);
                fma2a(acc[16+4*hh+2], gg, vb.x);
                fma2a(acc[16+4*hh+3], gg, vb.y);
            }
        }
        __syncthreads();
    }

    // ---- cross-lane butterfly sum of (l, acc) ----
    #pragma unroll
    for (int off = 16; off >= 1; off >>= 1){
        #pragma unroll
        for (int i = 0; i < 8; i++)
            l[i] += __shfl_xor_sync(0xffffffffu, l[i], off);
        #pragma unroll
        for (int i = 0; i < 32; i++)
            add2a(acc[i], __shfl_xor_sync(0xffffffffu, acc[i], off));
    }

    if (lane == 0){
        #pragma unroll
        for (int r = 0; r < 2; r++){
            #pragma unroll
            for (int hh = 0; hh < 4; hh++){
                const int H = hg*4 + hh;
                float inv = __fdividef(1.f, l[r*4 + hh]);
                #pragma unroll
                for (int d2 = 0; d2 < 4; d2++){
                    float2 u = unpack2(acc[r*16 + 4*hh + d2]);
                    y_s[(r0 + r)*64 + H*8 + d2*2]     = u.x * inv;
                    y_s[(r0 + r)*64 + H*8 + d2*2 + 1] = u.y * inv;
                }
            }
        }
    }
    __syncthreads();

    // ---- LN2 over (y + h_in): warp w handles row w (8 rows) ----
    {
        const float* hrow = hin + (size_t)(b*512 + q0 + w) * 64;
        float x0 = y_s[w*64 + lane]      + hrow[lane];
        float x1 = y_s[w*64 + lane + 32] + hrow[lane + 32];
        float s = x0 + x1, sq = x0*x0 + x1*x1;
        #pragma unroll
        for (int o = 16; o >= 1; o >>= 1){
            s  += __shfl_xor_sync(0xffffffffu, s, o);
            sq += __shfl_xor_sync(0xffffffffu, sq, o);
        }
        float mean = s * (1.f/64.f);
        float var  = sq * (1.f/64.f) - mean*mean;
        float rs = rsqrtf(var + EPSV);
        z_s[w*64 + lane]      = (x0 - mean) * rs * g2[lane]      + b2[lane];
        z_s[w*64 + lane + 32] = (x1 - mean) * rs * g2[lane + 32] + b2[lane + 32];
    }
    __syncthreads();

    // ---- hidden = relu(z @ w1)  [8 x 256], one column per thread ----
    {
        int jj = t;
        float a[8];
        #pragma unroll
        for (int r = 0; r < 8; r++) a[r] = 0.f;
        #pragma unroll 8
        for (int i = 0; i < 64; i++){
            float wv = w1[i*256 + jj];
            #pragma unroll
            for (int r = 0; r < 8; r++)
                a[r] = fmaf(z_s[r*64 + i], wv, a[r]);
        }
        #pragma unroll
        for (int r = 0; r < 8; r++)
            hid_s[r*256 + jj] = fmaxf(a[r], 0.f);
    }
    __syncthreads();

    // ---- out = hidden @ w2 + y : two output elements per thread ----
    {
        int d = t & 63, r = t >> 6;   // rows r and r+4
        float a0 = 0.f, a1 = 0.f;
        #pragma unroll 8
        for (int j = 0; j < 256; j++){
            float wv = w2[j*64 + d];
            a0 = fmaf(hid_s[r*256 + j],       wv, a0);
            a1 = fmaf(hid_s[(r+4)*256 + j],   wv, a1);
        }
        out[((size_t)(b*512 + q0 + r)) * 64 + d]     = a0 + y_s[r*64 + d];
        out[((size_t)(b*512 + q0 + r + 4)) * 64 + d] = a1 + y_s[(r+4)*64 + d];
    }
}

extern "C" void kernel_launch(void* const* d_in, const int* in_sizes, int n_in,
                              void* d_out, int out_size)
{
    const float* h  = (const float*)d_in[0];
    const float* e  = (const float*)d_in[1];
    const float* Wh = (const float*)d_in[2];
    const float* We = (const float*)d_in[3];
    const float* w1 = (const float*)d_in[4];
    const float* w2 = (const float*)d_in[5];
    const float* g1 = (const float*)d_in[6];
    const float* b1 = (const float*)d_in[7];
    const float* g2 = (const float*)d_in[8];
    const float* b2 = (const float*)d_in[9];
    float* out = (float*)d_out;

    cudaFuncSetAttribute(attn_kernel, cudaFuncAttributeMaxDynamicSharedMemorySize, 192512);

    qkv_kernel<<<2048, 64>>>(h, Wh, g1, b1);
    attn_kernel<<<256, 256, 192512>>>(e, We, h, w1, w2, g2, b2, out);
}